// round 8
// baseline (speedup 1.0000x reference)
#include <cuda_runtime.h>
#include <cstdint>

#define H      100
#define NBATCH 4096
#define SEQ    512
#define TB     32
#define NBLK   (NBATCH / TB)   // 128
#define NTHREADS 800           // 50 hp-groups * 16 batch-groups (25 warps)

// smem (u64 units):
//   Wp [100][200] u64 : Wp[k*200 + hp*4 + ty] = (W[ty*100+2hp][k], W[ty*100+2hp+1][k])
//   Hd 2 x [100][32] u64 : h duplicated (h,h) per batch, double buffered
#define WP_U64 (100 * 200)     // 20000 u64 = 160,000 B
#define HD_U64 (100 * 32)      // 3200 u64 per buffer
#define SMEM_BYTES ((WP_U64 + 2 * HD_U64) * 8)  // 211,200 B

typedef unsigned long long u64;

__device__ __forceinline__ void fma2(u64 &d, u64 a, u64 b) {
    asm("fma.rn.f32x2 %0, %1, %2, %0;" : "+l"(d) : "l"(a), "l"(b));
}
__device__ __forceinline__ u64 pk(float x, float y) {
    u64 r; asm("mov.b64 %0, {%1, %2};" : "=l"(r) : "f"(x), "f"(y)); return r;
}
__device__ __forceinline__ float2 upk(u64 v) {
    float2 r; asm("mov.b64 {%0, %1}, %2;" : "=f"(r.x), "=f"(r.y) : "l"(v)); return r;
}
__device__ __forceinline__ float tanh_mufu(float v) {
    float r; asm("tanh.approx.f32 %0, %1;" : "=f"(r) : "f"(v)); return r;
}
__device__ __forceinline__ float sig_mufu(float v) {
    return fmaf(0.5f, tanh_mufu(0.5f * v), 0.5f);
}

__global__ void __launch_bounds__(NTHREADS, 1)
lstm_kernel(const float* __restrict__ x,     // [512][4096]
            const float* __restrict__ Wih,   // [400]
            const float* __restrict__ Whh,   // [400][100]
            const float* __restrict__ bih,   // [400]
            const float* __restrict__ bhh,   // [400]
            const float* __restrict__ Wlin,  // [100]
            const float* __restrict__ blin,  // [1]
            float* __restrict__ out)         // [4096]
{
    extern __shared__ u64 sm[];
    u64* Wp = sm;              // [k*200 + hp*4 + ty]
    u64* Hd = sm + WP_U64;     // [buf*HD_U64 + k*32 + b], entry = (h_b, h_b)

    const int tid = threadIdx.x;
    const int hp  = tid >> 4;   // 0..49  (hidden pair: hu 2hp, 2hp+1)
    const int bg  = tid & 15;   // 0..15  (batch pair: batches bg*2, bg*2+1)

    // ---- Stage W_hh: pairs over adjacent hidden units, per gate type ----
    for (int idx = tid; idx < WP_U64; idx += NTHREADS) {
        int k  = idx / 200;
        int q  = idx % 200;
        int ph = q >> 2;
        int ty = q & 3;
        int row0 = ty * 100 + 2 * ph;
        Wp[idx] = pk(Whh[row0 * 100 + k], Whh[(row0 + 1) * 100 + k]);
    }
    // zero both h buffers (h0 = 0)
    for (int idx = tid; idx < 2 * HD_U64; idx += NTHREADS)
        Hd[idx] = 0ull;

    // ---- per-thread constants: bias sums + W_ih for my 8 gate rows ----
    float bs[2][4], wi[2][4];  // [u][ty], types: 0=i 1=f 2=g 3=o
    #pragma unroll
    for (int u = 0; u < 2; u++) {
        int hu = 2 * hp + u;
        #pragma unroll
        for (int ty = 0; ty < 4; ty++) {
            int j = ty * 100 + hu;
            bs[u][ty] = bih[j] + bhh[j];
            wi[u][ty] = Wih[j];
        }
    }
    float c[2][2];  // cell state [u][b]
    #pragma unroll
    for (int u = 0; u < 2; u++)
        #pragma unroll
        for (int b = 0; b < 2; b++) c[u][b] = 0.f;

    const int bbase = blockIdx.x * TB + bg * 2;  // my 2 batches
    __syncthreads();

    // ---- recurrence over 512 steps ----
    for (int t = 0; t < SEQ; t++) {
        const u64* hcur = Hd + ((t & 1) ? HD_U64 : 0);
        u64*       hnxt = Hd + ((t & 1) ? 0 : HD_U64);

        // x for my 2 batches (consumed only in epilogue -> latency hidden)
        float2 xv = *(const float2*)(x + (size_t)t * NBATCH + bbase);

        u64 acc[4][2];  // acc[ty][b] = f32x2 over (hu 2hp, 2hp+1)
        #pragma unroll
        for (int ty = 0; ty < 4; ty++)
            #pragma unroll
            for (int b = 0; b < 2; b++) acc[ty][b] = 0ull;

        #pragma unroll 4
        for (int k = 0; k < H; k++) {
            const ulonglong2 w01 = *(const ulonglong2*)(Wp + k * 200 + hp * 4);      // ty 0,1
            const ulonglong2 w23 = *(const ulonglong2*)(Wp + k * 200 + hp * 4 + 2);  // ty 2,3
            const ulonglong2 hd  = *(const ulonglong2*)(hcur + k * 32 + bg * 2);     // (h0,h0),(h1,h1)
            fma2(acc[0][0], w01.x, hd.x);
            fma2(acc[0][1], w01.x, hd.y);
            fma2(acc[1][0], w01.y, hd.x);
            fma2(acc[1][1], w01.y, hd.y);
            fma2(acc[2][0], w23.x, hd.x);
            fma2(acc[2][1], w23.x, hd.y);
            fma2(acc[3][0], w23.y, hd.x);
            fma2(acc[3][1], w23.y, hd.y);
        }

        // ---- epilogue: gates -> activations -> c,h update ----
        float hn[2][2];
        #pragma unroll
        for (int b = 0; b < 2; b++) {
            float xb = b ? xv.y : xv.x;
            float2 gI = upk(acc[0][b]);
            float2 gF = upk(acc[1][b]);
            float2 gG = upk(acc[2][b]);
            float2 gO = upk(acc[3][b]);
            #pragma unroll
            for (int u = 0; u < 2; u++) {
                float vi = (u ? gI.y : gI.x) + fmaf(wi[u][0], xb, bs[u][0]);
                float vf = (u ? gF.y : gF.x) + fmaf(wi[u][1], xb, bs[u][1]);
                float vg = (u ? gG.y : gG.x) + fmaf(wi[u][2], xb, bs[u][2]);
                float vo = (u ? gO.y : gO.x) + fmaf(wi[u][3], xb, bs[u][3]);
                float si = sig_mufu(vi);
                float sf = sig_mufu(vf);
                float so = sig_mufu(vo);
                float tg = tanh_mufu(vg);
                float cn = fmaf(sf, c[u][b], si * tg);
                c[u][b] = cn;
                hn[u][b] = so * tanh_mufu(cn);
            }
        }
        // store h duplicated: one STS.128 per hidden unit
        #pragma unroll
        for (int u = 0; u < 2; u++) {
            int hu = 2 * hp + u;
            ulonglong2 s;
            s.x = pk(hn[u][0], hn[u][0]);
            s.y = pk(hn[u][1], hn[u][1]);
            *(ulonglong2*)(hnxt + hu * 32 + bg * 2) = s;
        }
        __syncthreads();
    }

    // ---- linear head: out[b] = h_T[b] . W_lin + b_lin ----
    if (tid < TB) {
        const u64* hfin = Hd;  // SEQ even -> final state in buffer 0
        float acc = blin[0];
        #pragma unroll 4
        for (int k = 0; k < H; k++)
            acc = fmaf(upk(hfin[k * 32 + tid]).x, __ldg(Wlin + k), acc);
        out[blockIdx.x * TB + tid] = acc;
    }
}

extern "C" void kernel_launch(void* const* d_in, const int* in_sizes, int n_in,
                              void* d_out, int out_size) {
    const float* x    = (const float*)d_in[0];
    const float* Wih  = (const float*)d_in[1];
    const float* Whh  = (const float*)d_in[2];
    const float* bih  = (const float*)d_in[3];
    const float* bhh  = (const float*)d_in[4];
    const float* Wlin = (const float*)d_in[5];
    const float* blin = (const float*)d_in[6];

    cudaFuncSetAttribute(lstm_kernel, cudaFuncAttributeMaxDynamicSharedMemorySize, SMEM_BYTES);
    lstm_kernel<<<NBLK, NTHREADS, SMEM_BYTES>>>(x, Wih, Whh, bih, bhh, Wlin, blin,
                                                (float*)d_out);
}

// round 9
// speedup vs baseline: 1.4393x; 1.4393x over previous
#include <cuda_runtime.h>
#include <cstdint>

#define H      100
#define NBATCH 4096
#define SEQ    512
#define TB     28
#define NBLK   148
#define NTHREADS 352           // 11 warps; active threads: 50 hp * 7 bg = 350
#define NACT   350

// smem (u64 units):
//   Wp [100][200] u64 : Wp[k*200 + hp*4 + ty] = (W[ty*100+2hp][k], W[ty*100+2hp+1][k])
//   Hd 2 x [100][28] f32 : h plain floats, double buffered (row stride 112B)
#define WP_U64 (100 * 200)     // 20000 u64 = 160,000 B
#define HD_F   (100 * TB)      // 2800 floats per buffer
#define SMEM_BYTES (WP_U64 * 8 + 2 * HD_F * 4)  // 182,400 B

typedef unsigned long long u64;

__device__ __forceinline__ void fma2(u64 &d, u64 a, u64 b) {
    asm("fma.rn.f32x2 %0, %1, %2, %0;" : "+l"(d) : "l"(a), "l"(b));
}
__device__ __forceinline__ u64 pk(float x, float y) {
    u64 r; asm("mov.b64 %0, {%1, %2};" : "=l"(r) : "f"(x), "f"(y)); return r;
}
__device__ __forceinline__ float2 upk(u64 v) {
    float2 r; asm("mov.b64 {%0, %1}, %2;" : "=f"(r.x), "=f"(r.y) : "l"(v)); return r;
}
__device__ __forceinline__ float tanh_mufu(float v) {
    float r; asm("tanh.approx.f32 %0, %1;" : "=f"(r) : "f"(v)); return r;
}
__device__ __forceinline__ float sig_mufu(float v) {
    return fmaf(0.5f, tanh_mufu(0.5f * v), 0.5f);
}

__global__ void __launch_bounds__(NTHREADS, 1)
lstm_kernel(const float* __restrict__ x,     // [512][4096]
            const float* __restrict__ Wih,   // [400]
            const float* __restrict__ Whh,   // [400][100]
            const float* __restrict__ bih,   // [400]
            const float* __restrict__ bhh,   // [400]
            const float* __restrict__ Wlin,  // [100]
            const float* __restrict__ blin,  // [1]
            float* __restrict__ out)         // [4096]
{
    extern __shared__ u64 sm[];
    u64*   Wp = sm;                       // [k*200 + hp*4 + ty]
    float* Hd = (float*)(sm + WP_U64);    // [buf*HD_F + k*28 + b]

    const int tid = threadIdx.x;
    const bool act = (tid < NACT);
    const int hp  = tid / 7;    // 0..49  (hidden pair: hu 2hp, 2hp+1)
    const int bg  = tid % 7;    // 0..6   (batch quad within the 28-batch tile)

    // ---- Stage W_hh: pairs over adjacent hidden units, per gate type ----
    for (int idx = tid; idx < WP_U64; idx += NTHREADS) {
        int k  = idx / 200;
        int q  = idx % 200;
        int ph = q >> 2;
        int ty = q & 3;
        int row0 = ty * 100 + 2 * ph;
        Wp[idx] = pk(Whh[row0 * 100 + k], Whh[(row0 + 1) * 100 + k]);
    }
    // zero both h buffers (h0 = 0)
    for (int idx = tid; idx < 2 * HD_F; idx += NTHREADS)
        Hd[idx] = 0.f;

    // ---- per-thread constants: bias sums + W_ih for my 8 gate rows ----
    float bs[2][4], wi[2][4];  // [u][ty], types: 0=i 1=f 2=g 3=o
    if (act) {
        #pragma unroll
        for (int u = 0; u < 2; u++) {
            int hu = 2 * hp + u;
            #pragma unroll
            for (int ty = 0; ty < 4; ty++) {
                int j = ty * 100 + hu;
                bs[u][ty] = bih[j] + bhh[j];
                wi[u][ty] = Wih[j];
            }
        }
    }
    float c[2][4];  // cell state [u][b]
    #pragma unroll
    for (int u = 0; u < 2; u++)
        #pragma unroll
        for (int b = 0; b < 4; b++) c[u][b] = 0.f;

    const int bbase = blockIdx.x * TB + bg * 4;  // my 4 batches (global)
    const bool full4 = (bbase + 4 <= NBATCH);
    __syncthreads();

    // ---- recurrence over 512 steps ----
    for (int t = 0; t < SEQ; t++) {
        const float* hcur = Hd + ((t & 1) ? HD_F : 0);
        float*       hnxt = Hd + ((t & 1) ? 0 : HD_F);

        if (act) {
            // x for my 4 batches (consumed only in epilogue -> latency hidden)
            float4 xv;
            if (full4) {
                xv = *(const float4*)(x + (size_t)t * NBATCH + bbase);
            } else {
                xv.x = (bbase + 0 < NBATCH) ? x[(size_t)t * NBATCH + bbase + 0] : 0.f;
                xv.y = (bbase + 1 < NBATCH) ? x[(size_t)t * NBATCH + bbase + 1] : 0.f;
                xv.z = (bbase + 2 < NBATCH) ? x[(size_t)t * NBATCH + bbase + 2] : 0.f;
                xv.w = (bbase + 3 < NBATCH) ? x[(size_t)t * NBATCH + bbase + 3] : 0.f;
            }

            u64 acc[4][4];  // acc[ty][b] = f32x2 over (hu 2hp, 2hp+1)
            #pragma unroll
            for (int ty = 0; ty < 4; ty++)
                #pragma unroll
                for (int b = 0; b < 4; b++) acc[ty][b] = 0ull;

            #pragma unroll 5
            for (int k = 0; k < H; k++) {
                const ulonglong2 w01 = *(const ulonglong2*)(Wp + k * 200 + hp * 4);      // ty 0,1
                const ulonglong2 w23 = *(const ulonglong2*)(Wp + k * 200 + hp * 4 + 2);  // ty 2,3
                const float4 h0 = *(const float4*)(hcur + k * TB + bg * 4);
                u64 hd[4];
                hd[0] = pk(h0.x, h0.x); hd[1] = pk(h0.y, h0.y);
                hd[2] = pk(h0.z, h0.z); hd[3] = pk(h0.w, h0.w);
                #pragma unroll
                for (int b = 0; b < 4; b++) {
                    fma2(acc[0][b], w01.x, hd[b]);
                    fma2(acc[1][b], w01.y, hd[b]);
                    fma2(acc[2][b], w23.x, hd[b]);
                    fma2(acc[3][b], w23.y, hd[b]);
                }
            }

            // ---- epilogue: gates -> activations -> c,h update ----
            float hn[2][4];
            #pragma unroll
            for (int b = 0; b < 4; b++) {
                float xb = (b == 0) ? xv.x : (b == 1) ? xv.y : (b == 2) ? xv.z : xv.w;
                float2 gI = upk(acc[0][b]);
                float2 gF = upk(acc[1][b]);
                float2 gG = upk(acc[2][b]);
                float2 gO = upk(acc[3][b]);
                #pragma unroll
                for (int u = 0; u < 2; u++) {
                    float vi = (u ? gI.y : gI.x) + fmaf(wi[u][0], xb, bs[u][0]);
                    float vf = (u ? gF.y : gF.x) + fmaf(wi[u][1], xb, bs[u][1]);
                    float vg = (u ? gG.y : gG.x) + fmaf(wi[u][2], xb, bs[u][2]);
                    float vo = (u ? gO.y : gO.x) + fmaf(wi[u][3], xb, bs[u][3]);
                    float si = sig_mufu(vi);
                    float sf = sig_mufu(vf);
                    float so = sig_mufu(vo);
                    float tg = tanh_mufu(vg);
                    float cn = fmaf(sf, c[u][b], si * tg);
                    c[u][b] = cn;
                    hn[u][b] = so * tanh_mufu(cn);
                }
            }
            // vectorized h store (block-local; padding batches harmless)
            #pragma unroll
            for (int u = 0; u < 2; u++) {
                int hu = 2 * hp + u;
                *(float4*)(hnxt + hu * TB + bg * 4) =
                    make_float4(hn[u][0], hn[u][1], hn[u][2], hn[u][3]);
            }
        }
        __syncthreads();
    }

    // ---- linear head: out[b] = h_T[b] . W_lin + b_lin ----
    if (tid < TB && blockIdx.x * TB + tid < NBATCH) {
        const float* hfin = Hd;  // SEQ even -> final state in buffer 0
        float acc = blin[0];
        #pragma unroll 4
        for (int k = 0; k < H; k++)
            acc = fmaf(hfin[k * TB + tid], __ldg(Wlin + k), acc);
        out[blockIdx.x * TB + tid] = acc;
    }
}

extern "C" void kernel_launch(void* const* d_in, const int* in_sizes, int n_in,
                              void* d_out, int out_size) {
    const float* x    = (const float*)d_in[0];
    const float* Wih  = (const float*)d_in[1];
    const float* Whh  = (const float*)d_in[2];
    const float* bih  = (const float*)d_in[3];
    const float* bhh  = (const float*)d_in[4];
    const float* Wlin = (const float*)d_in[5];
    const float* blin = (const float*)d_in[6];

    cudaFuncSetAttribute(lstm_kernel, cudaFuncAttributeMaxDynamicSharedMemorySize, SMEM_BYTES);
    lstm_kernel<<<NBLK, NTHREADS, SMEM_BYTES>>>(x, Wih, Whh, bih, bhh, Wlin, blin,
                                                (float*)d_out);
}

// round 10
// speedup vs baseline: 1.4581x; 1.0131x over previous
#include <cuda_runtime.h>
#include <cstdint>

#define H      100
#define NBATCH 4096
#define SEQ    512
#define TB     28
#define NBLK   148
#define NTHREADS 352           // 11 warps; active threads: 50 hp * 7 bg = 350
#define NACT   350

// smem (u64 units):
//   Wp [100][208] u64 : row stride 208 u64 = 1664 B = 13*128 (128B-aligned rows)
//                       Wp[k*208 + hp*4 + ty] = (W[ty*100+2hp][k], W[ty*100+2hp+1][k])
//   Hd 2 x [100][32] f32 : h plain floats, row stride 32 floats = 128 B (aligned);
//                          cols 0..27 real batches, 28..31 padding
#define WP_STRIDE 208
#define WP_U64 (100 * WP_STRIDE)   // 20800 u64 = 166,400 B
#define HD_STRIDE 32
#define HD_F   (100 * HD_STRIDE)   // 3200 floats per buffer
#define SMEM_BYTES (WP_U64 * 8 + 2 * HD_F * 4)  // 192,000 B

typedef unsigned long long u64;

__device__ __forceinline__ void fma2(u64 &d, u64 a, u64 b) {
    asm("fma.rn.f32x2 %0, %1, %2, %0;" : "+l"(d) : "l"(a), "l"(b));
}
__device__ __forceinline__ u64 pk(float x, float y) {
    u64 r; asm("mov.b64 %0, {%1, %2};" : "=l"(r) : "f"(x), "f"(y)); return r;
}
__device__ __forceinline__ float2 upk(u64 v) {
    float2 r; asm("mov.b64 {%0, %1}, %2;" : "=f"(r.x), "=f"(r.y) : "l"(v)); return r;
}
__device__ __forceinline__ float tanh_mufu(float v) {
    float r; asm("tanh.approx.f32 %0, %1;" : "=f"(r) : "f"(v)); return r;
}
__device__ __forceinline__ float sig_mufu(float v) {
    return fmaf(0.5f, tanh_mufu(0.5f * v), 0.5f);
}

__global__ void __launch_bounds__(NTHREADS, 1)
lstm_kernel(const float* __restrict__ x,     // [512][4096]
            const float* __restrict__ Wih,   // [400]
            const float* __restrict__ Whh,   // [400][100]
            const float* __restrict__ bih,   // [400]
            const float* __restrict__ bhh,   // [400]
            const float* __restrict__ Wlin,  // [100]
            const float* __restrict__ blin,  // [1]
            float* __restrict__ out)         // [4096]
{
    extern __shared__ u64 sm[];
    u64*   Wp = sm;                       // [k*208 + hp*4 + ty]
    float* Hd = (float*)(sm + WP_U64);    // [buf*HD_F + k*32 + b]

    const int tid = threadIdx.x;
    const bool act = (tid < NACT);
    const int hp  = tid / 7;    // 0..49  (hidden pair: hu 2hp, 2hp+1)
    const int bg  = tid % 7;    // 0..6   (batch quad within the 28-batch tile)

    // ---- Stage W_hh: pairs over adjacent hidden units, per gate type ----
    for (int idx = tid; idx < 100 * 200; idx += NTHREADS) {
        int k  = idx / 200;
        int q  = idx % 200;
        int ph = q >> 2;
        int ty = q & 3;
        int row0 = ty * 100 + 2 * ph;
        Wp[k * WP_STRIDE + q] = pk(Whh[row0 * 100 + k], Whh[(row0 + 1) * 100 + k]);
    }
    // zero both h buffers (h0 = 0; padding cols too)
    for (int idx = tid; idx < 2 * HD_F; idx += NTHREADS)
        Hd[idx] = 0.f;

    // ---- per-thread constants: bias sums + W_ih for my 8 gate rows ----
    float bs[2][4], wi[2][4];  // [u][ty], types: 0=i 1=f 2=g 3=o
    if (act) {
        #pragma unroll
        for (int u = 0; u < 2; u++) {
            int hu = 2 * hp + u;
            #pragma unroll
            for (int ty = 0; ty < 4; ty++) {
                int j = ty * 100 + hu;
                bs[u][ty] = bih[j] + bhh[j];
                wi[u][ty] = Wih[j];
            }
        }
    }
    float c[2][4];  // cell state [u][b]
    #pragma unroll
    for (int u = 0; u < 2; u++)
        #pragma unroll
        for (int b = 0; b < 4; b++) c[u][b] = 0.f;

    const int bbase = blockIdx.x * TB + bg * 4;  // my 4 batches (global)
    const bool full4 = (bbase + 4 <= NBATCH);
    __syncthreads();

    // ---- recurrence over 512 steps ----
    for (int t = 0; t < SEQ; t++) {
        const float* hcur = Hd + ((t & 1) ? HD_F : 0);
        float*       hnxt = Hd + ((t & 1) ? 0 : HD_F);

        if (act) {
            // x for my 4 batches (consumed only in epilogue -> latency hidden)
            float4 xv;
            if (full4) {
                xv = *(const float4*)(x + (size_t)t * NBATCH + bbase);
            } else {
                xv.x = (bbase + 0 < NBATCH) ? x[(size_t)t * NBATCH + bbase + 0] : 0.f;
                xv.y = (bbase + 1 < NBATCH) ? x[(size_t)t * NBATCH + bbase + 1] : 0.f;
                xv.z = (bbase + 2 < NBATCH) ? x[(size_t)t * NBATCH + bbase + 2] : 0.f;
                xv.w = (bbase + 3 < NBATCH) ? x[(size_t)t * NBATCH + bbase + 3] : 0.f;
            }

            u64 acc[4][4];  // acc[ty][b] = f32x2 over (hu 2hp, 2hp+1)
            #pragma unroll
            for (int ty = 0; ty < 4; ty++)
                #pragma unroll
                for (int b = 0; b < 4; b++) acc[ty][b] = 0ull;

            #pragma unroll 10
            for (int k = 0; k < H; k++) {
                const ulonglong2 w01 = *(const ulonglong2*)(Wp + k * WP_STRIDE + hp * 4);      // ty 0,1
                const ulonglong2 w23 = *(const ulonglong2*)(Wp + k * WP_STRIDE + hp * 4 + 2);  // ty 2,3
                const float4 h0 = *(const float4*)(hcur + k * HD_STRIDE + bg * 4);
                u64 hd[4];
                hd[0] = pk(h0.x, h0.x); hd[1] = pk(h0.y, h0.y);
                hd[2] = pk(h0.z, h0.z); hd[3] = pk(h0.w, h0.w);
                #pragma unroll
                for (int b = 0; b < 4; b++) {
                    fma2(acc[0][b], w01.x, hd[b]);
                    fma2(acc[1][b], w01.y, hd[b]);
                    fma2(acc[2][b], w23.x, hd[b]);
                    fma2(acc[3][b], w23.y, hd[b]);
                }
            }

            // ---- epilogue: gates -> activations -> c,h update ----
            float hn[2][4];
            #pragma unroll
            for (int b = 0; b < 4; b++) {
                float xb = (b == 0) ? xv.x : (b == 1) ? xv.y : (b == 2) ? xv.z : xv.w;
                float2 gI = upk(acc[0][b]);
                float2 gF = upk(acc[1][b]);
                float2 gG = upk(acc[2][b]);
                float2 gO = upk(acc[3][b]);
                #pragma unroll
                for (int u = 0; u < 2; u++) {
                    float vi = (u ? gI.y : gI.x) + fmaf(wi[u][0], xb, bs[u][0]);
                    float vf = (u ? gF.y : gF.x) + fmaf(wi[u][1], xb, bs[u][1]);
                    float vg = (u ? gG.y : gG.x) + fmaf(wi[u][2], xb, bs[u][2]);
                    float vo = (u ? gO.y : gO.x) + fmaf(wi[u][3], xb, bs[u][3]);
                    float si = sig_mufu(vi);
                    float sf = sig_mufu(vf);
                    float so = sig_mufu(vo);
                    float tg = tanh_mufu(vg);
                    float cn = fmaf(sf, c[u][b], si * tg);
                    c[u][b] = cn;
                    hn[u][b] = so * tanh_mufu(cn);
                }
            }
            // vectorized h store (block-local; padding batches harmless)
            #pragma unroll
            for (int u = 0; u < 2; u++) {
                int hu = 2 * hp + u;
                *(float4*)(hnxt + hu * HD_STRIDE + bg * 4) =
                    make_float4(hn[u][0], hn[u][1], hn[u][2], hn[u][3]);
            }
        }
        __syncthreads();
    }

    // ---- linear head: out[b] = h_T[b] . W_lin + b_lin ----
    if (tid < TB && blockIdx.x * TB + tid < NBATCH) {
        const float* hfin = Hd;  // SEQ even -> final state in buffer 0
        float acc = blin[0];
        #pragma unroll 4
        for (int k = 0; k < H; k++)
            acc = fmaf(hfin[k * HD_STRIDE + tid], __ldg(Wlin + k), acc);
        out[blockIdx.x * TB + tid] = acc;
    }
}

extern "C" void kernel_launch(void* const* d_in, const int* in_sizes, int n_in,
                              void* d_out, int out_size) {
    const float* x    = (const float*)d_in[0];
    const float* Wih  = (const float*)d_in[1];
    const float* Whh  = (const float*)d_in[2];
    const float* bih  = (const float*)d_in[3];
    const float* bhh  = (const float*)d_in[4];
    const float* Wlin = (const float*)d_in[5];
    const float* blin = (const float*)d_in[6];

    cudaFuncSetAttribute(lstm_kernel, cudaFuncAttributeMaxDynamicSharedMemorySize, SMEM_BYTES);
    lstm_kernel<<<NBLK, NTHREADS, SMEM_BYTES>>>(x, Wih, Whh, bih, bhh, Wlin, blin,
                                                (float*)d_out);
}

// round 13
// speedup vs baseline: 1.5301x; 1.0494x over previous
#include <cuda_runtime.h>
#include <cstdint>

#define H      100
#define NBATCH 4096
#define SEQ    512
#define TB     28
#define NBLK   148
#define NTHREADS 224           // 7 warps; active: 50 hp * 4 bg = 200
#define NACT   200

// smem (u64 units):
//   Wp [100][208] u64 : row stride 208 u64 = 1664 B (128B-aligned rows)
//                       Wp[k*208 + hp*4 + ty] = (W[ty*100+2hp][k], W[ty*100+2hp+1][k])
//   Hd 2 x [4][101][8] f32 (bg-major): Hd[buf][bg][k][j] = h of batch bg*7+j (j=0..6)
//       bg stride 808 floats (808 % 32 = 8 -> bank-conflict-free across bg)
#define WP_STRIDE 208
#define WP_U64 (100 * WP_STRIDE)     // 20800 u64 = 166,400 B
#define HD_BG  808                   // floats per bg group
#define HD_F   (4 * HD_BG)           // 3232 floats per buffer
#define SMEM_BYTES (WP_U64 * 8 + 2 * HD_F * 4)  // 192,256 B

typedef unsigned long long u64;

__device__ __forceinline__ void fma2(u64 &d, u64 a, u64 b) {
    asm("fma.rn.f32x2 %0, %1, %2, %0;" : "+l"(d) : "l"(a), "l"(b));
}
__device__ __forceinline__ u64 pk(float x, float y) {
    u64 r; asm("mov.b64 %0, {%1, %2};" : "=l"(r) : "f"(x), "f"(y)); return r;
}
__device__ __forceinline__ float2 upk(u64 v) {
    float2 r; asm("mov.b64 {%0, %1}, %2;" : "=f"(r.x), "=f"(r.y) : "l"(v)); return r;
}
__device__ __forceinline__ float tanh_mufu(float v) {
    float r; asm("tanh.approx.f32 %0, %1;" : "=f"(r) : "f"(v)); return r;
}
__device__ __forceinline__ float sig_mufu(float v) {
    return fmaf(0.5f, tanh_mufu(0.5f * v), 0.5f);
}

__global__ void __launch_bounds__(NTHREADS, 1)
lstm_kernel(const float* __restrict__ x,     // [512][4096]
            const float* __restrict__ Wih,   // [400]
            const float* __restrict__ Whh,   // [400][100]
            const float* __restrict__ bih,   // [400]
            const float* __restrict__ bhh,   // [400]
            const float* __restrict__ Wlin,  // [100]
            const float* __restrict__ blin,  // [1]
            float* __restrict__ out)         // [4096]
{
    extern __shared__ u64 sm[];
    u64*   Wp = sm;                       // [k*208 + hp*4 + ty]
    float* Hd = (float*)(sm + WP_U64);    // [buf*HD_F + bg*808 + k*8 + j]

    const int tid = threadIdx.x;
    const int hp  = tid >> 2;   // 0..55; active if < 50 (hidden pair: hu 2hp, 2hp+1)
    const int bg  = tid & 3;    // 0..3  (batch septet: batches bg*7 .. bg*7+6)
    const bool act = (hp < 50);

    // ---- Stage W_hh: pairs over adjacent hidden units, per gate type ----
    for (int idx = tid; idx < 100 * 200; idx += NTHREADS) {
        int k  = idx / 200;
        int q  = idx % 200;
        int ph = q >> 2;
        int ty = q & 3;
        int row0 = ty * 100 + 2 * ph;
        Wp[k * WP_STRIDE + q] = pk(Whh[row0 * 100 + k], Whh[(row0 + 1) * 100 + k]);
    }
    // zero both h buffers (h0 = 0; padding too)
    for (int idx = tid; idx < 2 * HD_F; idx += NTHREADS)
        Hd[idx] = 0.f;

    // ---- per-thread constants: bias sums + W_ih for my 8 gate rows ----
    float bs[2][4], wi[2][4];  // [u][ty], types: 0=i 1=f 2=g 3=o
    if (act) {
        #pragma unroll
        for (int u = 0; u < 2; u++) {
            int hu = 2 * hp + u;
            #pragma unroll
            for (int ty = 0; ty < 4; ty++) {
                int j = ty * 100 + hu;
                bs[u][ty] = bih[j] + bhh[j];
                wi[u][ty] = Wih[j];
            }
        }
    }
    float c[2][7];  // cell state [u][j]
    #pragma unroll
    for (int u = 0; u < 2; u++)
        #pragma unroll
        for (int j = 0; j < 7; j++) c[u][j] = 0.f;

    const int bbase = blockIdx.x * TB + bg * 7;      // my 7 batches (global)
    const float* hbase = Hd + bg * HD_BG;
    float*       sbase = Hd + bg * HD_BG;
    __syncthreads();

    // ---- recurrence over 512 steps ----
    for (int t = 0; t < SEQ; t++) {
        const int cur = (t & 1) ? HD_F : 0;
        const int nxt = (t & 1) ? 0 : HD_F;

        if (act) {
            // x for my 7 batches: scalar loads (bbase is NOT vector-aligned).
            // Consumed only in epilogue -> latency fully hidden by GEMM.
            float xv[7];
            #pragma unroll
            for (int j = 0; j < 7; j++)
                xv[j] = (bbase + j < NBATCH) ? x[(size_t)t * NBATCH + bbase + j] : 0.f;

            u64 acc[4][7];  // acc[ty][j] = f32x2 over (hu 2hp, 2hp+1)
            #pragma unroll
            for (int ty = 0; ty < 4; ty++)
                #pragma unroll
                for (int j = 0; j < 7; j++) acc[ty][j] = 0ull;

            #pragma unroll 10
            for (int k = 0; k < H; k++) {
                const ulonglong2 w01 = *(const ulonglong2*)(Wp + k * WP_STRIDE + hp * 4);
                const ulonglong2 w23 = *(const ulonglong2*)(Wp + k * WP_STRIDE + hp * 4 + 2);
                const float4 ha = *(const float4*)(hbase + cur + k * 8);      // j 0..3
                const float2 hb = *(const float2*)(hbase + cur + k * 8 + 4);  // j 4,5
                const float  hc = hbase[cur + k * 8 + 6];                     // j 6
                u64 hd[7];
                hd[0] = pk(ha.x, ha.x); hd[1] = pk(ha.y, ha.y);
                hd[2] = pk(ha.z, ha.z); hd[3] = pk(ha.w, ha.w);
                hd[4] = pk(hb.x, hb.x); hd[5] = pk(hb.y, hb.y);
                hd[6] = pk(hc, hc);
                #pragma unroll
                for (int j = 0; j < 7; j++) {
                    fma2(acc[0][j], w01.x, hd[j]);
                    fma2(acc[1][j], w01.y, hd[j]);
                    fma2(acc[2][j], w23.x, hd[j]);
                    fma2(acc[3][j], w23.y, hd[j]);
                }
            }

            // ---- epilogue: gates -> activations -> c,h update ----
            float hn[2][7];
            #pragma unroll
            for (int j = 0; j < 7; j++) {
                float xb = xv[j];
                float2 gI = upk(acc[0][j]);
                float2 gF = upk(acc[1][j]);
                float2 gG = upk(acc[2][j]);
                float2 gO = upk(acc[3][j]);
                #pragma unroll
                for (int u = 0; u < 2; u++) {
                    float vi = (u ? gI.y : gI.x) + fmaf(wi[u][0], xb, bs[u][0]);
                    float vf = (u ? gF.y : gF.x) + fmaf(wi[u][1], xb, bs[u][1]);
                    float vg = (u ? gG.y : gG.x) + fmaf(wi[u][2], xb, bs[u][2]);
                    float vo = (u ? gO.y : gO.x) + fmaf(wi[u][3], xb, bs[u][3]);
                    float si = sig_mufu(vi);
                    float sf = sig_mufu(vf);
                    float so = sig_mufu(vo);
                    float tg = tanh_mufu(vg);
                    float cn = fmaf(sf, c[u][j], si * tg);
                    c[u][j] = cn;
                    hn[u][j] = so * tanh_mufu(cn);
                }
            }
            // h store: 2 rows x 7 floats into my bg slab (16B-aligned bases)
            #pragma unroll
            for (int u = 0; u < 2; u++) {
                int hu = 2 * hp + u;
                *(float4*)(sbase + nxt + hu * 8) =
                    make_float4(hn[u][0], hn[u][1], hn[u][2], hn[u][3]);
                *(float2*)(sbase + nxt + hu * 8 + 4) = make_float2(hn[u][4], hn[u][5]);
                sbase[nxt + hu * 8 + 6] = hn[u][6];
            }
        }
        __syncthreads();
    }

    // ---- linear head: out[b] = h_T[b] . W_lin + b_lin ----
    if (tid < TB && blockIdx.x * TB + tid < NBATCH) {
        const int fbg = tid / 7, fj = tid % 7;
        const float* hfin = Hd + fbg * HD_BG;  // SEQ even -> buffer 0
        float acc = blin[0];
        #pragma unroll 4
        for (int k = 0; k < H; k++)
            acc = fmaf(hfin[k * 8 + fj], __ldg(Wlin + k), acc);
        out[blockIdx.x * TB + tid] = acc;
    }
}

extern "C" void kernel_launch(void* const* d_in, const int* in_sizes, int n_in,
                              void* d_out, int out_size) {
    const float* x    = (const float*)d_in[0];
    const float* Wih  = (const float*)d_in[1];
    const float* Whh  = (const float*)d_in[2];
    const float* bih  = (const float*)d_in[3];
    const float* bhh  = (const float*)d_in[4];
    const float* Wlin = (const float*)d_in[5];
    const float* blin = (const float*)d_in[6];

    cudaFuncSetAttribute(lstm_kernel, cudaFuncAttributeMaxDynamicSharedMemorySize, SMEM_BYTES);
    lstm_kernel<<<NBLK, NTHREADS, SMEM_BYTES>>>(x, Wih, Whh, bih, bhh, Wlin, blin,
                                                (float*)d_out);
}